// round 2
// baseline (speedup 1.0000x reference)
#include <cuda_runtime.h>
#include <cuda_fp16.h>
#include <stdint.h>

#define K_DIM 4096
#define N_DIM 14336
#define BATCH 8
#define TK (K_DIM/16)      // 256 k-tiles
#define TN (N_DIM/16)      // 896 n-tiles
#define KSPLIT 8
#define NSTRIPS (TN/2)     // 448 strips of 32 columns

// Scratch (device globals; no allocation allowed)
__device__ __align__(16) float g_xh[K_DIM * BATCH];            // [k][batch], k-major
__device__ __align__(16) float g_yp[KSPLIT * BATCH * N_DIM];   // partial sums [ks][b][n]
__device__ int g_mode;   // 1 = promoted (float32 / int32-per-u16), 0 = native (fp16 / packed u16)

// ---------------------------------------------------------------------------
// Probe: decide whether the trellis buffer is packed u16 (native) or one u16
// per int32 word (promoted). Promoted values are all < 65536 -> high bits 0.
// Packed random u16 pairs have nonzero high halves with certainty over 256K words.
// ---------------------------------------------------------------------------
__global__ void k_probe(const int* __restrict__ t) {
    __shared__ int flag;
    if (threadIdx.x == 0) flag = 0;
    __syncthreads();
    int acc = 0;
    for (int i = threadIdx.x; i < (1 << 18); i += blockDim.x) acc |= t[i];
    if (acc & 0xFFFF0000) atomicOr(&flag, 1);
    __syncthreads();
    if (threadIdx.x == 0) g_mode = flag ? 0 : 1;
}

// ---------------------------------------------------------------------------
// Kernel 1: xh = Had128(x * suh), stored k-major [k][8]
// grid (32, 8), 128 threads
// ---------------------------------------------------------------------------
__global__ void k_had_in(const void* __restrict__ xv_, const void* __restrict__ suh_) {
    __shared__ float s[128];
    int t = threadIdx.x;
    int kb = blockIdx.x * 128;
    int row = blockIdx.y;
    int mode = g_mode;
    float v;
    if (mode) {
        v = ((const float*)xv_)[row * K_DIM + kb + t] * ((const float*)suh_)[kb + t];
    } else {
        v = __half2float(((const __half*)xv_)[row * K_DIM + kb + t]) *
            __half2float(((const __half*)suh_)[kb + t]);
    }
#pragma unroll
    for (int h = 1; h < 128; h <<= 1) {
        s[t] = v;
        __syncthreads();
        float o = s[t ^ h];
        __syncthreads();
        v = (t & h) ? (o - v) : (v + o);
    }
    g_xh[(kb + t) * BATCH + row] = v * 0.08838834764831845f;   // 1/sqrt(128)
}

// ---------------------------------------------------------------------------
// Kernel 2: main dequant + GEMM
// grid = NSTRIPS*KSPLIT blocks, 128 threads (4 warps)
// Each warp: 32 columns (2 adjacent trellis tiles), TK/KSPLIT/4 = 8 k-tiles.
// ---------------------------------------------------------------------------
__global__ void __launch_bounds__(128) k_main(const void* __restrict__ trellis_) {
    int bid = blockIdx.x;
    int strip = bid >> 3;          // 0..447
    int ks = bid & 7;              // k-slice
    int tid = threadIdx.x;
    int warp = tid >> 5, lane = tid & 31;
    int tn0 = strip * 2;
    int mode = g_mode;

    int tsel = lane >> 4;          // which of the two tiles
    int c = lane & 15;             // column within tile
    int c3 = 3 * c;
    int c3h = c3 >> 4;             // word offset within row (0..2)
    int sh = 16 - (c3 & 15);       // shift (1..16)
    unsigned int cbase = (unsigned)(tsel * 48 + c3h);

    __shared__ unsigned int rawS[4][48];   // 96 u16 (2 tiles) per warp
    __shared__ unsigned int combS[4][96];  // precombined 32-bit windows
    __shared__ float4 xS4[4][32];          // x tile: 16 k-rows x 8 batch

    // batch accumulators as 4 packed f32x2
    unsigned long long a0 = 0, a1 = 0, a2 = 0, a3 = 0;

    int tkBase = ks * (TK / KSPLIT) + warp * (TK / KSPLIT / 4);
#pragma unroll 1
    for (int tki = 0; tki < TK / KSPLIT / 4; ++tki) {
        int tk = tkBase + tki;
        size_t tbase = ((size_t)tk * TN + tn0) * 48;    // in u16-elements
        float4 xv = ((const float4*)(g_xh + tk * 128))[lane];

        unsigned short* r16 = (unsigned short*)rawS[warp];
        if (mode) {
            // promoted: 96 int32 words, one u16 each
            const int* tp32 = (const int*)trellis_ + tbase;
#pragma unroll
            for (int j = 0; j < 3; j++) {
                int idx = lane + j * 32;
                r16[idx] = (unsigned short)tp32[idx];
            }
        } else {
            // native: 48 u32 words = 96 packed u16
            const unsigned int* tp =
                (const unsigned int*)((const unsigned short*)trellis_ + tbase);
            rawS[warp][lane] = tp[lane];
            if (lane < 16) rawS[warp][32 + lane] = tp[32 + lane];
        }
        __syncwarp();

#pragma unroll
        for (int j = 0; j < 3; j++) {
            int idx = lane + j * 32;               // 0..95
            int tile = (idx >= 48) ? 1 : 0;
            int w = idx - tile * 48;
            int wn = (w + 1 == 48) ? 0 : (w + 1);  // tail-biting wrap
            combS[warp][idx] =
                ((unsigned int)r16[tile * 48 + w] << 16) | (unsigned int)r16[tile * 48 + wn];
        }
        xS4[warp][lane] = xv;
        __syncwarp();

        const unsigned long long* xp = (const unsigned long long*)&xS4[warp][0];
#pragma unroll
        for (int r = 0; r < 16; r++) {
            unsigned int comb = combS[warp][cbase + 3 * r];
            unsigned int st = (comb >> sh) & 0xFFFFu;
            unsigned int z = st * 89226354u + 64248484u;
            z &= 0x8FFF8FFFu;
            half2 h2 = *reinterpret_cast<half2*>(&z);
            float wv = __low2float(h2) + __high2float(h2);
            unsigned long long wp;
            asm("mov.b64 %0, {%1, %1};" : "=l"(wp) : "f"(wv));
            unsigned long long x0 = xp[r * 4 + 0];
            unsigned long long x1 = xp[r * 4 + 1];
            unsigned long long x2 = xp[r * 4 + 2];
            unsigned long long x3 = xp[r * 4 + 3];
            asm("fma.rn.f32x2 %0, %1, %2, %0;" : "+l"(a0) : "l"(wp), "l"(x0));
            asm("fma.rn.f32x2 %0, %1, %2, %0;" : "+l"(a1) : "l"(wp), "l"(x1));
            asm("fma.rn.f32x2 %0, %1, %2, %0;" : "+l"(a2) : "l"(wp), "l"(x2));
            asm("fma.rn.f32x2 %0, %1, %2, %0;" : "+l"(a3) : "l"(wp), "l"(x3));
        }
        __syncwarp();
    }

    // ---- deterministic block reduction over the 4 warps ----
    __shared__ float redS[4][256];   // [warp][col*8 + b]
    float f[8];
    asm("mov.b64 {%0, %1}, %2;" : "=f"(f[0]), "=f"(f[1]) : "l"(a0));
    asm("mov.b64 {%0, %1}, %2;" : "=f"(f[2]), "=f"(f[3]) : "l"(a1));
    asm("mov.b64 {%0, %1}, %2;" : "=f"(f[4]), "=f"(f[5]) : "l"(a2));
    asm("mov.b64 {%0, %1}, %2;" : "=f"(f[6]), "=f"(f[7]) : "l"(a3));
#pragma unroll
    for (int b = 0; b < 8; b++) redS[warp][lane * 8 + b] = f[b];
    __syncthreads();

#pragma unroll
    for (int i = tid; i < 256; i += 128) {
        int col = i & 31, b = i >> 5;
        int idx = col * 8 + b;
        float s = redS[0][idx] + redS[1][idx] + redS[2][idx] + redS[3][idx];
        g_yp[((size_t)ks * BATCH + b) * N_DIM + strip * 32 + col] = s;
    }
}

// ---------------------------------------------------------------------------
// Kernel 3: sum partials, Had128 over N, *svh + bias -> output
// grid (112, 8), 128 threads
// ---------------------------------------------------------------------------
__global__ void k_epi(const void* __restrict__ svh_, const void* __restrict__ bias_,
                      void* __restrict__ out_) {
    __shared__ float s[128];
    int t = threadIdx.x;
    int nb = blockIdx.x * 128;
    int row = blockIdx.y;
    int n = nb + t;
    int mode = g_mode;
    float v = 0.f;
#pragma unroll
    for (int ksl = 0; ksl < KSPLIT; ksl++)
        v += g_yp[((size_t)ksl * BATCH + row) * N_DIM + n];
#pragma unroll
    for (int h = 1; h < 128; h <<= 1) {
        s[t] = v;
        __syncthreads();
        float o = s[t ^ h];
        __syncthreads();
        v = (t & h) ? (o - v) : (v + o);
    }
    v *= 0.08838834764831845f;
    if (mode) {
        float o = v * ((const float*)svh_)[n] + ((const float*)bias_)[n];
        ((float*)out_)[row * N_DIM + n] = o;
    } else {
        float o = v * __half2float(((const __half*)svh_)[n]) +
                  __half2float(((const __half*)bias_)[n]);
        ((__half*)out_)[row * N_DIM + n] = __float2half(o);
    }
}

// ---------------------------------------------------------------------------
extern "C" void kernel_launch(void* const* d_in, const int* in_sizes, int n_in,
                              void* d_out, int out_size) {
    const void* x = d_in[0];
    const void* trellis = d_in[1];
    const void* suh = d_in[2];
    const void* svh = d_in[3];
    const void* bias = d_in[4];

    k_probe<<<1, 256>>>((const int*)trellis);
    k_had_in<<<dim3(K_DIM / 128, BATCH), 128>>>(x, suh);
    k_main<<<NSTRIPS * KSPLIT, 128>>>(trellis);
    k_epi<<<dim3(N_DIM / 128, BATCH), 128>>>(svh, bias, d_out);
}

// round 3
// speedup vs baseline: 1.3678x; 1.3678x over previous
#include <cuda_runtime.h>
#include <cuda_fp16.h>
#include <stdint.h>

#define K_DIM 4096
#define N_DIM 14336
#define BATCH 8
#define TK (K_DIM/16)      // 256 k-tiles
#define TN (N_DIM/16)      // 896 n-tiles
#define KSPLIT 8
#define NSTRIPS (TN/2)     // 448 strips of 32 columns

// Promoted dtypes confirmed in round 2: x/suh/svh/bias/out = float32,
// trellis = int32 (one u16 value per word).

// Scratch (device globals; no allocation allowed)
__device__ __align__(16) float g_xh[K_DIM * BATCH];            // [k][batch], k-major
__device__ __align__(16) float g_yp[KSPLIT * BATCH * N_DIM];   // partial sums [ks][b][n]

// ---------------------------------------------------------------------------
// Kernel 1: xh = Had128(x * suh), stored k-major [k][8]
// grid (32, 8), 128 threads. Shuffle butterflies for h<32, smem for h=32,64.
// ---------------------------------------------------------------------------
__global__ void k_had_in(const float* __restrict__ x, const float* __restrict__ suh) {
    __shared__ float s[128];
    int t = threadIdx.x;
    int kb = blockIdx.x * 128;
    int row = blockIdx.y;
    float v = x[row * K_DIM + kb + t] * suh[kb + t];
#pragma unroll
    for (int h = 1; h < 32; h <<= 1) {
        float o = __shfl_xor_sync(0xFFFFFFFFu, v, h);
        v = (t & h) ? (o - v) : (v + o);
    }
#pragma unroll
    for (int h = 32; h < 128; h <<= 1) {
        s[t] = v;
        __syncthreads();
        float o = s[t ^ h];
        __syncthreads();
        v = (t & h) ? (o - v) : (v + o);
    }
    g_xh[(kb + t) * BATCH + row] = v * 0.08838834764831845f;   // 1/sqrt(128)
}

// ---------------------------------------------------------------------------
// Kernel 2: main dequant + GEMM (launched twice, ksOfs = 0 and 4)
// grid = NSTRIPS*4 blocks, 128 threads (4 warps)
// Each warp: 32 columns (2 adjacent trellis tiles), 8 k-tiles.
// ---------------------------------------------------------------------------
__global__ void __launch_bounds__(128) k_main(const int* __restrict__ trellis, int ksOfs) {
    int bid = blockIdx.x;
    int strip = bid >> 2;            // 0..447
    int ks = ksOfs + (bid & 3);      // k-slice
    int tid = threadIdx.x;
    int warp = tid >> 5, lane = tid & 31;
    int tn0 = strip * 2;

    int tsel = lane >> 4;            // which of the two tiles
    int c = lane & 15;               // column within tile
    int c3 = 3 * c;
    int c3h = c3 >> 4;               // word offset within row (0..2)
    int sh = 16 - (c3 & 15);         // shift (1..16)
    unsigned int cbase = (unsigned)(tsel * 48 + c3h);

    __shared__ unsigned int rawS[4][48];   // 96 u16 (2 tiles) per warp
    __shared__ unsigned int combS[4][96];  // precombined 32-bit windows
    __shared__ float4 xS4[4][32];          // x tile: 16 k-rows x 8 batch

    // batch accumulators as 4 packed f32x2
    unsigned long long a0 = 0, a1 = 0, a2 = 0, a3 = 0;

    int tkBase = ks * (TK / KSPLIT) + warp * (TK / KSPLIT / 4);
#pragma unroll 1
    for (int tki = 0; tki < TK / KSPLIT / 4; ++tki) {
        int tk = tkBase + tki;
        size_t tbase = ((size_t)tk * TN + tn0) * 48;    // in words
        float4 xv = ((const float4*)(g_xh + tk * 128))[lane];

        unsigned short* r16 = (unsigned short*)rawS[warp];
        const int* tp32 = trellis + tbase;              // 96 contiguous int32
#pragma unroll
        for (int j = 0; j < 3; j++) {
            int idx = lane + j * 32;
            r16[idx] = (unsigned short)tp32[idx];
        }
        __syncwarp();

#pragma unroll
        for (int j = 0; j < 3; j++) {
            int idx = lane + j * 32;               // 0..95
            int tile = (idx >= 48) ? 1 : 0;
            int w = idx - tile * 48;
            int wn = (w + 1 == 48) ? 0 : (w + 1);  // tail-biting wrap
            combS[warp][idx] = __byte_perm((unsigned int)r16[tile * 48 + wn],
                                           (unsigned int)r16[tile * 48 + w], 0x5410);
        }
        xS4[warp][lane] = xv;
        __syncwarp();

        const unsigned long long* xp = (const unsigned long long*)&xS4[warp][0];
#pragma unroll
        for (int r = 0; r < 16; r++) {
            unsigned int comb = combS[warp][cbase + 3 * r];
            unsigned int st = (comb >> sh) & 0xFFFFu;
            unsigned int z = st * 89226354u + 64248484u;
            z &= 0x8FFF8FFFu;
            half2 h2 = *reinterpret_cast<half2*>(&z);
            // sum halves in fp16 (exact for |v|<2^-13; <=2^-12 rel rounding
            // above), then ONE F2F to fp32 instead of two.
            half hs = __hadd(__low2half(h2), __high2half(h2));
            float wv = __half2float(hs);
            unsigned long long wp;
            asm("mov.b64 %0, {%1, %1};" : "=l"(wp) : "f"(wv));
            unsigned long long x0 = xp[r * 4 + 0];
            unsigned long long x1 = xp[r * 4 + 1];
            unsigned long long x2 = xp[r * 4 + 2];
            unsigned long long x3 = xp[r * 4 + 3];
            asm("fma.rn.f32x2 %0, %1, %2, %0;" : "+l"(a0) : "l"(wp), "l"(x0));
            asm("fma.rn.f32x2 %0, %1, %2, %0;" : "+l"(a1) : "l"(wp), "l"(x1));
            asm("fma.rn.f32x2 %0, %1, %2, %0;" : "+l"(a2) : "l"(wp), "l"(x2));
            asm("fma.rn.f32x2 %0, %1, %2, %0;" : "+l"(a3) : "l"(wp), "l"(x3));
        }
        __syncwarp();
    }

    // ---- deterministic block reduction over the 4 warps ----
    __shared__ float redS[4][256];   // [warp][col*8 + b]
    float f[8];
    asm("mov.b64 {%0, %1}, %2;" : "=f"(f[0]), "=f"(f[1]) : "l"(a0));
    asm("mov.b64 {%0, %1}, %2;" : "=f"(f[2]), "=f"(f[3]) : "l"(a1));
    asm("mov.b64 {%0, %1}, %2;" : "=f"(f[4]), "=f"(f[5]) : "l"(a2));
    asm("mov.b64 {%0, %1}, %2;" : "=f"(f[6]), "=f"(f[7]) : "l"(a3));
#pragma unroll
    for (int b = 0; b < 8; b++) redS[warp][lane * 8 + b] = f[b];
    __syncthreads();

#pragma unroll
    for (int i = tid; i < 256; i += 128) {
        int col = i & 31, b = i >> 5;
        int idx = col * 8 + b;
        float s = redS[0][idx] + redS[1][idx] + redS[2][idx] + redS[3][idx];
        g_yp[((size_t)ks * BATCH + b) * N_DIM + strip * 32 + col] = s;
    }
}

// ---------------------------------------------------------------------------
// Kernel 3: sum partials, Had128 over N, *svh + bias -> float32 out
// grid (112, 8), 128 threads
// ---------------------------------------------------------------------------
__global__ void k_epi(const float* __restrict__ svh, const float* __restrict__ bias,
                      float* __restrict__ out) {
    __shared__ float s[128];
    int t = threadIdx.x;
    int n = blockIdx.x * 128 + t;
    int row = blockIdx.y;
    float v = 0.f;
#pragma unroll
    for (int ksl = 0; ksl < KSPLIT; ksl++)
        v += g_yp[((size_t)ksl * BATCH + row) * N_DIM + n];
#pragma unroll
    for (int h = 1; h < 32; h <<= 1) {
        float o = __shfl_xor_sync(0xFFFFFFFFu, v, h);
        v = (t & h) ? (o - v) : (v + o);
    }
#pragma unroll
    for (int h = 32; h < 128; h <<= 1) {
        s[t] = v;
        __syncthreads();
        float o = s[t ^ h];
        __syncthreads();
        v = (t & h) ? (o - v) : (v + o);
    }
    v *= 0.08838834764831845f;
    out[row * N_DIM + n] = v * svh[n] + bias[n];
}

// ---------------------------------------------------------------------------
extern "C" void kernel_launch(void* const* d_in, const int* in_sizes, int n_in,
                              void* d_out, int out_size) {
    const float* x = (const float*)d_in[0];
    const int* trellis = (const int*)d_in[1];
    const float* suh = (const float*)d_in[2];
    const float* svh = (const float*)d_in[3];
    const float* bias = (const float*)d_in[4];
    float* out = (float*)d_out;

    k_had_in<<<dim3(K_DIM / 128, BATCH), 128>>>(x, suh);
    // two half-KSPLIT launches (also puts k_main at ncu's -s 5 capture slot)
    k_main<<<NSTRIPS * 4, 128>>>(trellis, 0);
    k_main<<<NSTRIPS * 4, 128>>>(trellis, 4);
    k_epi<<<dim3(N_DIM / 128, BATCH), 128>>>(svh, bias, out);
}

// round 4
// speedup vs baseline: 1.7529x; 1.2816x over previous
#include <cuda_runtime.h>
#include <cuda_fp16.h>
#include <stdint.h>

#define K_DIM 4096
#define N_DIM 14336
#define BATCH 8
#define TK (K_DIM/16)      // 256 k-tiles
#define TN (N_DIM/16)      // 896 n-tiles
#define KSPLIT 4
#define NSTRIPS (TN/2)     // 448 strips of 32 columns

// Promoted dtypes (confirmed): x/suh/svh/bias/out = float32, trellis = int32 (one u16/word).

// Scratch (device globals; no allocation allowed)
__device__ __align__(16) __half g_xh[K_DIM * BATCH];           // [k][8 halves], 16B per k-row
__device__ __align__(16) float g_yp[KSPLIT * BATCH * N_DIM];   // partials [ks][b][n]

// ---------------------------------------------------------------------------
// Kernel 1: xh = Had128(x * suh) -> fp16, k-major [k][8]
// ---------------------------------------------------------------------------
__global__ void k_had_in(const float* __restrict__ x, const float* __restrict__ suh) {
    __shared__ float s[128];
    int t = threadIdx.x;
    int kb = blockIdx.x * 128;
    int row = blockIdx.y;
    float v = x[row * K_DIM + kb + t] * suh[kb + t];
#pragma unroll
    for (int h = 1; h < 32; h <<= 1) {
        float o = __shfl_xor_sync(0xFFFFFFFFu, v, h);
        v = (t & h) ? (o - v) : (v + o);
    }
#pragma unroll
    for (int h = 32; h < 128; h <<= 1) {
        s[t] = v;
        __syncthreads();
        float o = s[t ^ h];
        __syncthreads();
        v = (t & h) ? (o - v) : (v + o);
    }
    g_xh[(kb + t) * BATCH + row] = __float2half(v * 0.08838834764831845f);
}

// ---------------------------------------------------------------------------
// Kernel 2: main dequant + GEMM. grid = NSTRIPS*KSPLIT, 128 threads (4 warps).
// Each warp: 32 columns (2 adjacent trellis tiles), 16 k-tiles.
// ---------------------------------------------------------------------------
__global__ void __launch_bounds__(128) k_main(const int* __restrict__ trellis) {
    int bid = blockIdx.x;
    int strip = bid >> 2;            // 0..447
    int ks = bid & 3;                // k-slice
    int tid = threadIdx.x;
    int warp = tid >> 5, lane = tid & 31;
    int tn0 = strip * 2;

    int tsel = lane >> 4;            // which of the two tiles
    int c = lane & 15;               // column within tile
    int c3 = 3 * c;
    int c3h = c3 >> 4;               // word offset within row (0..2)
    int sh = 16 - (c3 & 15);         // shift (1..16)
    unsigned int cbase = (unsigned)(tsel * 48 + c3h);

    __shared__ unsigned int rawS[4][48];   // 96 u16 (2 tiles) per warp
    __shared__ unsigned int combS[4][96];  // precombined 32-bit windows
    __shared__ uint4 xS[4][16];            // x tile: 16 k-rows x 8 fp16

    __half2 ah0 = __float2half2_rn(0.f), ah1 = ah0, ah2 = ah0, ah3 = ah0;
    float fa[8] = {0.f, 0.f, 0.f, 0.f, 0.f, 0.f, 0.f, 0.f};

    int tkBase = ks * (TK / KSPLIT) + warp * (TK / KSPLIT / 4);   // ks*64 + warp*16
#pragma unroll 1
    for (int tki = 0; tki < TK / KSPLIT / 4; ++tki) {             // 16 iters
        int tk = tkBase + tki;
        size_t tbase = ((size_t)tk * TN + tn0) * 48;              // in words

        unsigned short* r16 = (unsigned short*)rawS[warp];
        const int* tp32 = trellis + tbase;                        // 96 contiguous int32
#pragma unroll
        for (int j = 0; j < 3; j++) {
            int idx = lane + j * 32;
            r16[idx] = (unsigned short)tp32[idx];
        }
        if (lane < 16) xS[warp][lane] = ((const uint4*)g_xh)[tk * 16 + lane];
        __syncwarp();

#pragma unroll
        for (int j = 0; j < 3; j++) {
            int idx = lane + j * 32;               // 0..95
            int tile = (idx >= 48) ? 1 : 0;
            int w = idx - tile * 48;
            int wn = (w + 1 == 48) ? 0 : (w + 1);  // tail-biting wrap
            combS[warp][idx] = __byte_perm((unsigned int)r16[tile * 48 + wn],
                                           (unsigned int)r16[tile * 48 + w], 0x5410);
        }
        __syncwarp();

#pragma unroll
        for (int r = 0; r < 16; r++) {
            unsigned int comb = combS[warp][cbase + 3 * r];
            unsigned int st = (comb >> sh) & 0xFFFFu;
            unsigned int z = st * 89226354u + 64248484u;
            z &= 0x8FFF8FFFu;
            unsigned int zs = __byte_perm(z, z, 0x1032);      // swap 16-bit halves
            __half2 w2 = __hadd2(*(const __half2*)&z, *(const __half2*)&zs); // (lo+hi, lo+hi)
            uint4 xv = xS[warp][r];                           // LDS.128 broadcast
            ah0 = __hfma2(w2, *(const __half2*)&xv.x, ah0);
            ah1 = __hfma2(w2, *(const __half2*)&xv.y, ah1);
            ah2 = __hfma2(w2, *(const __half2*)&xv.z, ah2);
            ah3 = __hfma2(w2, *(const __half2*)&xv.w, ah3);
        }

        if (tki & 1) {   // flush fp16 accumulators to fp32 every 2 k-tiles
            float2 f;
            f = __half22float2(ah0); fa[0] += f.x; fa[1] += f.y;
            f = __half22float2(ah1); fa[2] += f.x; fa[3] += f.y;
            f = __half22float2(ah2); fa[4] += f.x; fa[5] += f.y;
            f = __half22float2(ah3); fa[6] += f.x; fa[7] += f.y;
            ah0 = __float2half2_rn(0.f); ah1 = ah0; ah2 = ah0; ah3 = ah0;
        }
        __syncwarp();
    }

    // ---- deterministic block reduction over the 4 warps ----
    __shared__ float redS[4][256];   // [warp][col*8 + b]
#pragma unroll
    for (int b = 0; b < 8; b++) redS[warp][lane * 8 + b] = fa[b];
    __syncthreads();

#pragma unroll
    for (int i = tid; i < 256; i += 128) {
        int col = i & 31, b = i >> 5;
        int idx = col * 8 + b;
        float s = redS[0][idx] + redS[1][idx] + redS[2][idx] + redS[3][idx];
        g_yp[((size_t)ks * BATCH + b) * N_DIM + strip * 32 + col] = s;
    }
}

// ---------------------------------------------------------------------------
// Kernel 3: sum partials, Had128 over N, *svh + bias -> float32 out
// ---------------------------------------------------------------------------
__global__ void k_epi(const float* __restrict__ svh, const float* __restrict__ bias,
                      float* __restrict__ out) {
    __shared__ float s[128];
    int t = threadIdx.x;
    int n = blockIdx.x * 128 + t;
    int row = blockIdx.y;
    float v = 0.f;
#pragma unroll
    for (int ksl = 0; ksl < KSPLIT; ksl++)
        v += g_yp[((size_t)ksl * BATCH + row) * N_DIM + n];
#pragma unroll
    for (int h = 1; h < 32; h <<= 1) {
        float o = __shfl_xor_sync(0xFFFFFFFFu, v, h);
        v = (t & h) ? (o - v) : (v + o);
    }
#pragma unroll
    for (int h = 32; h < 128; h <<= 1) {
        s[t] = v;
        __syncthreads();
        float o = s[t ^ h];
        __syncthreads();
        v = (t & h) ? (o - v) : (v + o);
    }
    v *= 0.08838834764831845f;
    out[row * N_DIM + n] = v * svh[n] + bias[n];
}

// ---------------------------------------------------------------------------
extern "C" void kernel_launch(void* const* d_in, const int* in_sizes, int n_in,
                              void* d_out, int out_size) {
    const float* x = (const float*)d_in[0];
    const int* trellis = (const int*)d_in[1];
    const float* suh = (const float*)d_in[2];
    const float* svh = (const float*)d_in[3];
    const float* bias = (const float*)d_in[4];
    float* out = (float*)d_out;

    k_had_in<<<dim3(K_DIM / 128, BATCH), 128>>>(x, suh);
    k_main<<<NSTRIPS * KSPLIT, 128>>>(trellis);
    k_epi<<<dim3(N_DIM / 128, BATCH), 128>>>(svh, bias, out);
}